// round 3
// baseline (speedup 1.0000x reference)
#include <cuda_runtime.h>
#include <cuda_bf16.h>
#include <cstdint>

#define NN   100000
#define EE   1000000
#define DIN  64
#define DH   128
#define DOUT 64
#define NPB1 8
#define NPB2 8

// Scratch (device globals — no allocation allowed).
__device__ float4 g_agg1[(size_t)NN * (DIN / 4)];   // 25.6 MB
__device__ float  g_cnt[NN];                        // 0.4 MB
__device__ float  g_h[(size_t)NN * DH];             // 51.2 MB
__device__ float4 g_y[(size_t)NN * (DOUT / 4)];     // 25.6 MB  (y = h @ W2l)
__device__ float4 g_agg2[(size_t)NN * (DOUT / 4)];  // 25.6 MB
__device__ int    g_is64;                           // edge_index dtype flag

__device__ __forceinline__ void red_add_v4(float4* addr, float4 v) {
    size_t gaddr = __cvta_generic_to_global(addr);
    asm volatile("red.global.add.v4.f32 [%0], {%1,%2,%3,%4};"
                 :: "l"(gaddr), "f"(v.x), "f"(v.y), "f"(v.z), "f"(v.w) : "memory");
}

// Index fetch tolerant of int32 vs int64 storage (flag set by detect_kernel).
__device__ __forceinline__ int load_idx(const int* __restrict__ ei, int pos, int is64) {
    int v = is64 ? ei[2 * pos] : ei[pos];   // little-endian low word for int64
    return min(max(v, 0), NN - 1);
}

// --------------------------------------------- detect edge_index storage width
__global__ void detect_kernel(const int* __restrict__ ei) {
    if (threadIdx.x == 0 && blockIdx.x == 0) {
        int is64 = 1;
        #pragma unroll 1
        for (int i = 1; i < 2048; i += 2)
            if (ei[i] != 0) { is64 = 0; break; }
        g_is64 = is64;
    }
}

// ---------------------------------------------------------------- zero scratch
__global__ void zero_kernel() {
    int i = blockIdx.x * blockDim.x + threadIdx.x;
    int stride = gridDim.x * blockDim.x;
    const float4 z = make_float4(0.f, 0.f, 0.f, 0.f);
    for (int k = i; k < NN * (DIN / 4); k += stride)  g_agg1[k] = z;
    for (int k = i; k < NN * (DOUT / 4); k += stride) g_agg2[k] = z;
    for (int k = i; k < NN; k += stride)              g_cnt[k]  = 0.f;
}

// ------------------------------------------------- scatter layer 1: agg1 += x[src]
// 16 lanes per edge, one float4 per lane (64 floats/row)
__global__ void scatter1_kernel(const float* __restrict__ x,
                                const int* __restrict__ ei) {
    int t = blockIdx.x * blockDim.x + threadIdx.x;
    int e = t >> 4;
    int lane = t & 15;
    if (e >= EE) return;
    int is64 = g_is64;
    int src = load_idx(ei, e, is64);
    int dst = load_idx(ei, EE + e, is64);
    const float4* xr = (const float4*)(x + (size_t)src * DIN);
    float4 v = xr[lane];
    red_add_v4(&g_agg1[(size_t)dst * (DIN / 4) + lane], v);
    if (lane == 0) atomicAdd(&g_cnt[dst], 1.0f);
}

// ------------------------------------------------- layer 1 + pre-multiply y = h@W2l
// h = relu(mean1 @ W1l + x @ W1r + b1);  y = h @ W2l
__global__ void __launch_bounds__(128, 2)
layer1_kernel(const float* __restrict__ x,
              const float* __restrict__ W1l,
              const float* __restrict__ W1r,
              const float* __restrict__ b1,
              const float* __restrict__ W2l) {
    extern __shared__ float smem[];
    float2* sWlr = (float2*)smem;                       // DIN*DH float2 (Wl,Wr interleaved)
    float*  sW2l = smem + 2 * DIN * DH;                 // DH*DOUT
    float*  sb1  = sW2l + DH * DOUT;                    // DH
    float2* sfeat = (float2*)(sb1 + DH);                // NPB1*DIN float2 (mean, x)
    float*  sh   = (float*)(sfeat + NPB1 * DIN);        // NPB1*DH

    int tid = threadIdx.x;  // 128
    for (int k = tid; k < DIN * DH; k += 128)
        sWlr[k] = make_float2(W1l[k], W1r[k]);
    for (int k = tid; k < DH * DOUT; k += 128)
        sW2l[k] = W2l[k];
    if (tid < DH) sb1[tid] = b1[tid];

    const float* agg1 = (const float*)g_agg1;
    int base = blockIdx.x * NPB1;
    for (int idx = tid; idx < NPB1 * DIN; idx += 128) {
        int n = idx / DIN, k = idx % DIN;
        int row = base + n;
        float m = 0.f, xv = 0.f;
        if (row < NN) {
            float inv = 1.0f / fmaxf(g_cnt[row], 1.0f);
            m  = agg1[(size_t)row * DIN + k] * inv;
            xv = x[(size_t)row * DIN + k];
        }
        sfeat[idx] = make_float2(m, xv);
    }
    __syncthreads();

    int j = tid;  // output column 0..127
    float acc[NPB1];
    #pragma unroll
    for (int n = 0; n < NPB1; n++) acc[n] = sb1[j];
    #pragma unroll
    for (int k = 0; k < DIN; k++) {
        float2 w = sWlr[k * DH + j];
        #pragma unroll
        for (int n = 0; n < NPB1; n++) {
            float2 f = sfeat[n * DIN + k];
            acc[n] = fmaf(f.x, w.x, fmaf(f.y, w.y, acc[n]));
        }
    }
    #pragma unroll
    for (int n = 0; n < NPB1; n++) {
        float h = fmaxf(acc[n], 0.f);
        sh[n * DH + j] = h;
        int row = base + n;
        if (row < NN) g_h[(size_t)row * DH + j] = h;
    }
    __syncthreads();

    // y = h @ W2l  (each thread: 1 node, 4 output columns stride 16)
    float* yout = (float*)g_y;
    int n2 = tid >> 4;
    int c0 = tid & 15;
    float ay[4] = {0.f, 0.f, 0.f, 0.f};
    #pragma unroll
    for (int k = 0; k < DH; k++) {
        float hv = sh[n2 * DH + k];
        #pragma unroll
        for (int i = 0; i < 4; i++)
            ay[i] = fmaf(hv, sW2l[k * DOUT + c0 + 16 * i], ay[i]);
    }
    int row2 = base + n2;
    if (row2 < NN) {
        #pragma unroll
        for (int i = 0; i < 4; i++)
            yout[(size_t)row2 * DOUT + c0 + 16 * i] = ay[i];
    }
}

// ------------------------------------------------- scatter layer 2: agg2 += y[src]
__global__ void scatter2_kernel(const int* __restrict__ ei) {
    int t = blockIdx.x * blockDim.x + threadIdx.x;
    int e = t >> 4;
    int lane = t & 15;
    if (e >= EE) return;
    int is64 = g_is64;
    int src = load_idx(ei, e, is64);
    int dst = load_idx(ei, EE + e, is64);
    float4 v = g_y[(size_t)src * (DOUT / 4) + lane];
    red_add_v4(&g_agg2[(size_t)dst * (DOUT / 4) + lane], v);
}

// ------------------------------------------------- layer 2: out = agg2/cnt + h@W2r + b2
__global__ void __launch_bounds__(128)
layer2_kernel(const float* __restrict__ W2r,
              const float* __restrict__ b2,
              float* __restrict__ out) {
    extern __shared__ float smem[];
    float* sW = smem;                 // DH*DOUT
    float* sb = sW + DH * DOUT;       // DOUT
    float* sh = sb + DOUT;            // NPB2*DH

    int tid = threadIdx.x;  // 128
    for (int k = tid; k < DH * DOUT; k += 128) sW[k] = W2r[k];
    if (tid < DOUT) sb[tid] = b2[tid];

    int base = blockIdx.x * NPB2;
    for (int idx = tid; idx < NPB2 * DH; idx += 128) {
        int n = idx / DH, k = idx % DH;
        int row = base + n;
        sh[idx] = (row < NN) ? g_h[(size_t)row * DH + k] : 0.f;
    }
    __syncthreads();

    const float* agg2 = (const float*)g_agg2;
    int n = tid >> 4;
    int c0 = tid & 15;
    float a[4] = {0.f, 0.f, 0.f, 0.f};
    #pragma unroll
    for (int k = 0; k < DH; k++) {
        float hv = sh[n * DH + k];
        #pragma unroll
        for (int i = 0; i < 4; i++)
            a[i] = fmaf(hv, sW[k * DOUT + c0 + 16 * i], a[i]);
    }
    int row = base + n;
    if (row < NN) {
        float inv = 1.0f / fmaxf(g_cnt[row], 1.0f);
        #pragma unroll
        for (int i = 0; i < 4; i++) {
            int c = c0 + 16 * i;
            out[(size_t)row * DOUT + c] =
                a[i] + agg2[(size_t)row * DOUT + c] * inv + sb[c];
        }
    }
}

// ---------------------------------------------------------------------------
extern "C" void kernel_launch(void* const* d_in, const int* in_sizes, int n_in,
                              void* d_out, int out_size) {
    const float* x   = (const float*)d_in[0];
    const float* W1l = (const float*)d_in[1];
    const float* W1r = (const float*)d_in[2];
    const float* b1  = (const float*)d_in[3];
    const float* W2l = (const float*)d_in[4];
    const float* W2r = (const float*)d_in[5];
    const float* b2  = (const float*)d_in[6];
    const int*   ei  = (const int*)d_in[7];   // int32 (likely) or int64 low/high pairs
    float* out = (float*)d_out;

    const int L1_SMEM = (2 * DIN * DH + DH * DOUT + DH + 2 * NPB1 * DIN + NPB1 * DH) * 4;
    const int L2_SMEM = (DH * DOUT + DOUT + NPB2 * DH) * 4;
    cudaFuncSetAttribute(layer1_kernel, cudaFuncAttributeMaxDynamicSharedMemorySize, L1_SMEM);

    detect_kernel<<<1, 32>>>(ei);
    zero_kernel<<<1024, 256>>>();
    scatter1_kernel<<<(EE * 16) / 256, 256>>>(x, ei);
    layer1_kernel<<<(NN + NPB1 - 1) / NPB1, 128, L1_SMEM>>>(x, W1l, W1r, b1, W2l);
    scatter2_kernel<<<(EE * 16) / 256, 256>>>(ei);
    layer2_kernel<<<(NN + NPB2 - 1) / NPB2, 128, L2_SMEM>>>(W2r, b2, out);
}

// round 4
// speedup vs baseline: 5.4151x; 5.4151x over previous
#include <cuda_runtime.h>
#include <cuda_bf16.h>
#include <cstdint>

#define NN   100000
#define EE   1000000
#define DIN  64
#define DH   128
#define DOUT 64
#define NT1  ((NN + 15) / 16)   // 6250 node tiles of 16

// Scratch (device globals — no allocation allowed).
__device__ float4 g_agg1[(size_t)NN * (DIN / 4)];   // 25.6 MB
__device__ float  g_cnt[NN];
__device__ float  g_inv[NN];
__device__ float  g_h[(size_t)NN * DH];             // 51.2 MB
__device__ float4 g_y[(size_t)NN * (DOUT / 4)];     // 25.6 MB
__device__ float4 g_agg2[(size_t)NN * (DOUT / 4)];  // 25.6 MB
__device__ int    g_src[EE];
__device__ int    g_dst[EE];
__device__ int    g_is64;

__device__ __forceinline__ void red_add_v4(float4* addr, float4 v) {
    size_t gaddr = __cvta_generic_to_global(addr);
    asm volatile("red.global.add.v4.f32 [%0], {%1,%2,%3,%4};"
                 :: "l"(gaddr), "f"(v.x), "f"(v.y), "f"(v.z), "f"(v.w) : "memory");
}

// --------------------------------------------- detect edge_index storage width
// int64 little-endian with values < 2^31 => every odd int32 word is 0.
__global__ void detect_kernel(const int* __restrict__ ei) {
    __shared__ int any_nonzero;
    if (threadIdx.x == 0) any_nonzero = 0;
    __syncthreads();
    int i = 1 + 2 * threadIdx.x;           // odd words 1..2047
    if (i < 2048 && ei[i] != 0) atomicExch(&any_nonzero, 1);
    __syncthreads();
    if (threadIdx.x == 0) g_is64 = any_nonzero ? 0 : 1;
}

// ---------------------------------------------------------------- zero scratch
__global__ void zero_kernel() {
    int i = blockIdx.x * blockDim.x + threadIdx.x;
    int stride = gridDim.x * blockDim.x;
    const float4 z = make_float4(0.f, 0.f, 0.f, 0.f);
    for (int k = i; k < NN * (DIN / 4); k += stride)  g_agg1[k] = z;
    for (int k = i; k < NN * (DOUT / 4); k += stride) g_agg2[k] = z;
    for (int k = i; k < NN; k += stride)              g_cnt[k]  = 0.f;
}

// --------------------------------- convert indices to int32 + degree counting
__global__ void convert_kernel(const int* __restrict__ ei) {
    int e = blockIdx.x * blockDim.x + threadIdx.x;
    if (e >= EE) return;
    int is64 = g_is64;
    int s = is64 ? ei[2 * e] : ei[e];
    int d = is64 ? ei[2 * (EE + e)] : ei[EE + e];
    s = min(max(s, 0), NN - 1);
    d = min(max(d, 0), NN - 1);
    g_src[e] = s;
    g_dst[e] = d;
    atomicAdd(&g_cnt[d], 1.0f);
}

__global__ void inv_kernel() {
    int i = blockIdx.x * blockDim.x + threadIdx.x;
    if (i < NN) g_inv[i] = 1.0f / fmaxf(g_cnt[i], 1.0f);
}

// ------------------------------------------------- scatter layer 1: agg1 += x[src]
__global__ void scatter1_kernel(const float* __restrict__ x) {
    int t = blockIdx.x * blockDim.x + threadIdx.x;
    int e = t >> 4;
    int lane = t & 15;
    if (e >= EE) return;
    int src = __ldg(&g_src[e]);
    int dst = __ldg(&g_dst[e]);
    const float4* xr = (const float4*)(x + (size_t)src * DIN);
    red_add_v4(&g_agg1[(size_t)dst * (DIN / 4) + lane], xr[lane]);
}

// ------------------------------------------------- layer 1 (persistent blocks)
// h = relu(mean1 @ W1l + x @ W1r + b1)
__global__ void __launch_bounds__(256, 3)
layer1_kernel(const float* __restrict__ x,
              const float* __restrict__ W1l,
              const float* __restrict__ W1r,
              const float* __restrict__ b1) {
    extern __shared__ float smem[];
    float2* sWlr = (float2*)smem;                 // DIN*DH float2 = 64KB
    float*  sb1  = smem + 2 * DIN * DH;           // DH
    float2* sfeat = (float2*)(sb1 + DH);          // 16*DIN float2 = 8KB

    int tid = threadIdx.x;  // 256
    for (int k = tid; k < DIN * DH; k += 256)
        sWlr[k] = make_float2(W1l[k], W1r[k]);
    if (tid < DH) sb1[tid] = b1[tid];

    const float* agg1 = (const float*)g_agg1;
    int j  = tid & 127;        // output column
    int ng = tid >> 7;         // node group 0/1 (8 nodes each)

    for (int tile = blockIdx.x; tile < NT1; tile += gridDim.x) {
        int base = tile * 16;
        __syncthreads();   // protect sfeat reuse from previous iteration
        for (int idx = tid; idx < 16 * DIN; idx += 256) {
            int n = idx >> 6, k = idx & 63;
            int row = base + n;
            float m = 0.f, xv = 0.f;
            if (row < NN) {
                float inv = g_inv[row];
                m  = agg1[(size_t)row * DIN + k] * inv;
                xv = x[(size_t)row * DIN + k];
            }
            sfeat[n * DIN + k] = make_float2(m, xv);
        }
        __syncthreads();

        float acc[8];
        #pragma unroll
        for (int n = 0; n < 8; n++) acc[n] = sb1[j];
        #pragma unroll 8
        for (int k = 0; k < DIN; k++) {
            float2 w = sWlr[k * DH + j];
            #pragma unroll
            for (int n = 0; n < 8; n++) {
                float2 f = sfeat[(ng * 8 + n) * DIN + k];
                acc[n] = fmaf(f.x, w.x, fmaf(f.y, w.y, acc[n]));
            }
        }
        #pragma unroll
        for (int n = 0; n < 8; n++) {
            int row = base + ng * 8 + n;
            if (row < NN) g_h[(size_t)row * DH + j] = fmaxf(acc[n], 0.f);
        }
    }
}

// ------------------------------------------------- y = h @ W2l (persistent)
__global__ void __launch_bounds__(256, 4)
ymul_kernel(const float* __restrict__ W2l) {
    extern __shared__ float smem[];
    float* sW = smem;            // DH*DOUT = 32KB
    float* sh = sW + DH * DOUT;  // 16*DH = 8KB

    int tid = threadIdx.x;
    for (int k = tid; k < DH * DOUT; k += 256) sW[k] = W2l[k];

    int n  = tid >> 4;          // node in tile 0..15
    int c0 = (tid & 15) * 4;    // 4 consecutive output cols

    for (int tile = blockIdx.x; tile < NT1; tile += gridDim.x) {
        int base = tile * 16;
        __syncthreads();
        for (int idx = tid; idx < 16 * DH; idx += 256) {
            int r = base + (idx >> 7);
            sh[idx] = (r < NN) ? g_h[(size_t)r * DH + (idx & 127)] : 0.f;
        }
        __syncthreads();

        float4 a = make_float4(0.f, 0.f, 0.f, 0.f);
        #pragma unroll 8
        for (int k = 0; k < DH; k++) {
            float hv = sh[n * DH + k];
            float4 w = *(const float4*)&sW[k * DOUT + c0];
            a.x = fmaf(hv, w.x, a.x); a.y = fmaf(hv, w.y, a.y);
            a.z = fmaf(hv, w.z, a.z); a.w = fmaf(hv, w.w, a.w);
        }
        int row = base + n;
        if (row < NN) g_y[(size_t)row * (DOUT / 4) + (c0 >> 2)] = a;
    }
}

// ------------------------------------------------- scatter layer 2: agg2 += y[src]
__global__ void scatter2_kernel() {
    int t = blockIdx.x * blockDim.x + threadIdx.x;
    int e = t >> 4;
    int lane = t & 15;
    if (e >= EE) return;
    int src = __ldg(&g_src[e]);
    int dst = __ldg(&g_dst[e]);
    float4 v = g_y[(size_t)src * (DOUT / 4) + lane];
    red_add_v4(&g_agg2[(size_t)dst * (DOUT / 4) + lane], v);
}

// ------------------------------------------------- layer 2 (persistent)
// out = agg2*inv + h @ W2r + b2
__global__ void __launch_bounds__(256, 4)
layer2_kernel(const float* __restrict__ W2r,
              const float* __restrict__ b2,
              float* __restrict__ out) {
    extern __shared__ float smem[];
    float* sW = smem;            // DH*DOUT = 32KB
    float* sb = sW + DH * DOUT;  // DOUT
    float* sh = sb + DOUT;       // 16*DH = 8KB

    int tid = threadIdx.x;
    for (int k = tid; k < DH * DOUT; k += 256) sW[k] = W2r[k];
    if (tid < DOUT) sb[tid] = b2[tid];

    int n  = tid >> 4;
    int c0 = (tid & 15) * 4;

    for (int tile = blockIdx.x; tile < NT1; tile += gridDim.x) {
        int base = tile * 16;
        __syncthreads();
        for (int idx = tid; idx < 16 * DH; idx += 256) {
            int r = base + (idx >> 7);
            sh[idx] = (r < NN) ? g_h[(size_t)r * DH + (idx & 127)] : 0.f;
        }
        __syncthreads();

        float4 a = make_float4(0.f, 0.f, 0.f, 0.f);
        #pragma unroll 8
        for (int k = 0; k < DH; k++) {
            float hv = sh[n * DH + k];
            float4 w = *(const float4*)&sW[k * DOUT + c0];
            a.x = fmaf(hv, w.x, a.x); a.y = fmaf(hv, w.y, a.y);
            a.z = fmaf(hv, w.z, a.z); a.w = fmaf(hv, w.w, a.w);
        }
        int row = base + n;
        if (row < NN) {
            float inv = g_inv[row];
            float4 g = g_agg2[(size_t)row * (DOUT / 4) + (c0 >> 2)];
            float4 o;
            o.x = a.x + g.x * inv + sb[c0 + 0];
            o.y = a.y + g.y * inv + sb[c0 + 1];
            o.z = a.z + g.z * inv + sb[c0 + 2];
            o.w = a.w + g.w * inv + sb[c0 + 3];
            *(float4*)&out[(size_t)row * DOUT + c0] = o;
        }
    }
}

// ---------------------------------------------------------------------------
extern "C" void kernel_launch(void* const* d_in, const int* in_sizes, int n_in,
                              void* d_out, int out_size) {
    const float* x   = (const float*)d_in[0];
    const float* W1l = (const float*)d_in[1];
    const float* W1r = (const float*)d_in[2];
    const float* b1  = (const float*)d_in[3];
    const float* W2l = (const float*)d_in[4];
    const float* W2r = (const float*)d_in[5];
    const float* b2  = (const float*)d_in[6];
    const int*   ei  = (const int*)d_in[7];
    float* out = (float*)d_out;

    const int L1_SMEM = (2 * DIN * DH + DH + 2 * 16 * DIN) * 4;        // ~72.5 KB
    const int YM_SMEM = (DH * DOUT + 16 * DH) * 4;                     // 40 KB
    const int L2_SMEM = (DH * DOUT + DOUT + 16 * DH) * 4;              // 40.3 KB
    cudaFuncSetAttribute(layer1_kernel, cudaFuncAttributeMaxDynamicSharedMemorySize, L1_SMEM);

    detect_kernel<<<1, 1024>>>(ei);
    zero_kernel<<<1024, 256>>>();
    convert_kernel<<<(EE + 255) / 256, 256>>>(ei);
    inv_kernel<<<(NN + 255) / 256, 256>>>();
    scatter1_kernel<<<(EE * 16) / 256, 256>>>(x);
    layer1_kernel<<<444, 256, L1_SMEM>>>(x, W1l, W1r, b1);
    ymul_kernel<<<592, 256, YM_SMEM>>>(W2l);
    scatter2_kernel<<<(EE * 16) / 256, 256>>>();
    layer2_kernel<<<592, 256, L2_SMEM>>>(W2r, b2, out);
}

// round 5
// speedup vs baseline: 7.9194x; 1.4624x over previous
#include <cuda_runtime.h>
#include <cuda_bf16.h>
#include <cstdint>

#define NN   100000
#define EE   1000000
#define DIN  64
#define DH   128
#define DOUT 64
#define NB_SCAN 391                     // ceil(NN/256)
#define NT1 ((NN + 31) / 32)            // layer1 tiles of 32 nodes
#define NTH ((NN + 63) / 64)            // hmul tiles of 64 nodes

// ----- device scratch (no allocation allowed) -----
__device__ int    g_is64;
__device__ int    g_cnti[NN];
__device__ int    g_bsum[NB_SCAN];
__device__ int    g_boff[NB_SCAN];
__device__ int    g_off[NN + 1];
__device__ int    g_cur[NN];
__device__ float  g_inv[NN];
__device__ int    g_src[EE];
__device__ int    g_dst[EE];
__device__ int    g_esrc[EE];                      // src sorted by dst bucket
__device__ float4 g_mean1[(size_t)NN * (DIN / 4)]; // mean of x over in-nbrs
__device__ float4 g_h4[(size_t)NN * (DH / 4)];     // hidden (relu)
__device__ float4 g_y[(size_t)NN * (DOUT / 4)];    // h @ W2l
__device__ float4 g_mean2[(size_t)NN * (DOUT / 4)];

// --------------------------------------------- detect edge_index storage width
__global__ void detect_kernel(const int* __restrict__ ei) {
    __shared__ int any_nonzero;
    if (threadIdx.x == 0) any_nonzero = 0;
    __syncthreads();
    int i = 1 + 2 * threadIdx.x;            // odd words 1..2047
    if (i < 2048 && ei[i] != 0) atomicExch(&any_nonzero, 1);
    __syncthreads();
    if (threadIdx.x == 0) g_is64 = any_nonzero ? 0 : 1;
}

__global__ void zero_cnt_kernel() {
    int i = blockIdx.x * blockDim.x + threadIdx.x;
    if (i < NN) g_cnti[i] = 0;
}

// --------------------------------- convert indices to int32 + degree histogram
__global__ void convert_kernel(const int* __restrict__ ei) {
    int e = blockIdx.x * blockDim.x + threadIdx.x;
    if (e >= EE) return;
    int is64 = g_is64;
    int s = is64 ? ei[2 * e] : ei[e];
    int d = is64 ? ei[2 * (EE + e)] : ei[EE + e];
    s = min(max(s, 0), NN - 1);
    d = min(max(d, 0), NN - 1);
    g_src[e] = s;
    g_dst[e] = d;
    atomicAdd(&g_cnti[d], 1);
}

// ------------------------------------------------------------- 3-phase scan
__global__ void scan1_kernel() {           // per-block sums of cnt
    __shared__ int s[256];
    int i = blockIdx.x * 256 + threadIdx.x;
    s[threadIdx.x] = (i < NN) ? g_cnti[i] : 0;
    __syncthreads();
    for (int d = 128; d > 0; d >>= 1) {
        if (threadIdx.x < d) s[threadIdx.x] += s[threadIdx.x + d];
        __syncthreads();
    }
    if (threadIdx.x == 0) g_bsum[blockIdx.x] = s[0];
}

__global__ void scan2_kernel() {           // exclusive scan of block sums
    __shared__ int s[512];
    int t = threadIdx.x;
    int orig = (t < NB_SCAN) ? g_bsum[t] : 0;
    s[t] = orig;
    __syncthreads();
    for (int d = 1; d < 512; d <<= 1) {
        int v = (t >= d) ? s[t - d] : 0;
        __syncthreads();
        s[t] += v;
        __syncthreads();
    }
    if (t < NB_SCAN) g_boff[t] = s[t] - orig;   // exclusive
}

__global__ void scan3_kernel() {           // per-element offsets + inv degree
    __shared__ int s[256];
    int t = threadIdx.x;
    int i = blockIdx.x * 256 + t;
    int c = (i < NN) ? g_cnti[i] : 0;
    s[t] = c;
    __syncthreads();
    for (int d = 1; d < 256; d <<= 1) {
        int v = (t >= d) ? s[t - d] : 0;
        __syncthreads();
        s[t] += v;
        __syncthreads();
    }
    if (i < NN) {
        int off = g_boff[blockIdx.x] + s[t] - c;   // exclusive
        g_off[i] = off;
        g_cur[i] = off;
        g_inv[i] = 1.0f / fmaxf((float)c, 1.0f);
    }
    if (i == 0) g_off[NN] = EE;
}

// -------------------------------------------------- bucket-place src by dst
__global__ void place_kernel() {
    int e = blockIdx.x * blockDim.x + threadIdx.x;
    if (e >= EE) return;
    int pos = atomicAdd(&g_cur[g_dst[e]], 1);
    g_esrc[pos] = g_src[e];
}

// ----------------------------------- gather-aggregate: mean1 = mean x[nbrs]
__global__ void __launch_bounds__(256)
agg1_kernel(const float* __restrict__ x) {
    int gwarp = (blockIdx.x * 256 + threadIdx.x) >> 5;
    int lane = threadIdx.x & 31;
    int nw = (gridDim.x * 256) >> 5;
    int chunk = lane & 15, par = lane >> 4;
    const float4* x4 = (const float4*)x;
    for (int node = gwarp; node < NN; node += nw) {
        int s = g_off[node], e = g_off[node + 1];
        float4 acc = make_float4(0.f, 0.f, 0.f, 0.f);
        for (int i = s + par; i < e; i += 2) {
            int src = g_esrc[i];
            float4 v = x4[(size_t)src * 16 + chunk];
            acc.x += v.x; acc.y += v.y; acc.z += v.z; acc.w += v.w;
        }
        acc.x += __shfl_down_sync(0xffffffffu, acc.x, 16);
        acc.y += __shfl_down_sync(0xffffffffu, acc.y, 16);
        acc.z += __shfl_down_sync(0xffffffffu, acc.z, 16);
        acc.w += __shfl_down_sync(0xffffffffu, acc.w, 16);
        if (par == 0) {
            float inv = g_inv[node];
            g_mean1[(size_t)node * 16 + chunk] =
                make_float4(acc.x * inv, acc.y * inv, acc.z * inv, acc.w * inv);
        }
    }
}

// ----------------------------------- gather-aggregate: mean2 = mean y[nbrs]
__global__ void __launch_bounds__(256)
agg2_kernel() {
    int gwarp = (blockIdx.x * 256 + threadIdx.x) >> 5;
    int lane = threadIdx.x & 31;
    int nw = (gridDim.x * 256) >> 5;
    int chunk = lane & 15, par = lane >> 4;
    for (int node = gwarp; node < NN; node += nw) {
        int s = g_off[node], e = g_off[node + 1];
        float4 acc = make_float4(0.f, 0.f, 0.f, 0.f);
        for (int i = s + par; i < e; i += 2) {
            int src = g_esrc[i];
            float4 v = g_y[(size_t)src * 16 + chunk];
            acc.x += v.x; acc.y += v.y; acc.z += v.z; acc.w += v.w;
        }
        acc.x += __shfl_down_sync(0xffffffffu, acc.x, 16);
        acc.y += __shfl_down_sync(0xffffffffu, acc.y, 16);
        acc.z += __shfl_down_sync(0xffffffffu, acc.z, 16);
        acc.w += __shfl_down_sync(0xffffffffu, acc.w, 16);
        if (par == 0) {
            float inv = g_inv[node];
            g_mean2[(size_t)node * 16 + chunk] =
                make_float4(acc.x * inv, acc.y * inv, acc.z * inv, acc.w * inv);
        }
    }
}

// -------------------------- layer 1: h = relu(mean1 @ W1l + x @ W1r + b1)
// 32-node tile, 256 thr = 8 node-groups(4) x 32 col-groups(4). 16 acc/thread.
__global__ void __launch_bounds__(256, 2)
layer1_kernel(const float* __restrict__ x,
              const float* __restrict__ W1l,
              const float* __restrict__ W1r,
              const float* __restrict__ b1) {
    extern __shared__ float smem[];
    float2* sWlr  = (float2*)smem;               // DIN*DH float2 = 64KB
    float*  sb1   = smem + 2 * DIN * DH;         // 128
    float2* sfeat = (float2*)(sb1 + DH);         // 32*DIN float2 = 16KB

    int tid = threadIdx.x;
    for (int k = tid; k < DIN * DH; k += 256)
        sWlr[k] = make_float2(W1l[k], W1r[k]);
    if (tid < DH) sb1[tid] = b1[tid];

    const float* mean1 = (const float*)g_mean1;
    float* h = (float*)g_h4;
    int j0 = (tid & 31) * 4;   // 4 cols
    int n0 = (tid >> 5) * 4;   // 4 nodes

    for (int tile = blockIdx.x; tile < NT1; tile += gridDim.x) {
        int base = tile * 32;
        __syncthreads();
        for (int idx = tid; idx < 32 * DIN; idx += 256) {
            int n = idx >> 6, k = idx & 63;
            int row = base + n;
            float m = 0.f, xv = 0.f;
            if (row < NN) {
                m  = mean1[(size_t)row * DIN + k];
                xv = x[(size_t)row * DIN + k];
            }
            sfeat[n * DIN + k] = make_float2(m, xv);
        }
        __syncthreads();

        float acc[4][4];
        #pragma unroll
        for (int i = 0; i < 4; i++)
            #pragma unroll
            for (int c = 0; c < 4; c++) acc[i][c] = sb1[j0 + c];

        #pragma unroll 8
        for (int k = 0; k < DIN; k++) {
            float2 w[4], f[4];
            #pragma unroll
            for (int c = 0; c < 4; c++) w[c] = sWlr[k * DH + j0 + c];
            #pragma unroll
            for (int i = 0; i < 4; i++) f[i] = sfeat[(n0 + i) * DIN + k];
            #pragma unroll
            for (int i = 0; i < 4; i++)
                #pragma unroll
                for (int c = 0; c < 4; c++)
                    acc[i][c] = fmaf(f[i].x, w[c].x, fmaf(f[i].y, w[c].y, acc[i][c]));
        }
        #pragma unroll
        for (int i = 0; i < 4; i++) {
            int row = base + n0 + i;
            if (row < NN) {
                float4 hv = make_float4(fmaxf(acc[i][0], 0.f), fmaxf(acc[i][1], 0.f),
                                        fmaxf(acc[i][2], 0.f), fmaxf(acc[i][3], 0.f));
                *(float4*)&h[(size_t)row * DH + j0] = hv;
            }
        }
    }
}

// ---------------- fused: y = h @ W2l ; out_partial = h @ W2r (no bias yet)
// 64-node tile, 256 thr = 16 node-groups(4) x 16 col-groups(4). 32 acc/thread.
__global__ void __launch_bounds__(256, 2)
hmul_kernel(const float* __restrict__ W2l,
            const float* __restrict__ W2r,
            float* __restrict__ out) {
    extern __shared__ float smem[];
    float* sWl = smem;                  // DH*DOUT = 32KB
    float* sWr = sWl + DH * DOUT;       // 32KB
    float* sh  = sWr + DH * DOUT;       // 64*DH = 32KB

    int tid = threadIdx.x;
    for (int k = tid; k < DH * DOUT; k += 256) { sWl[k] = W2l[k]; sWr[k] = W2r[k]; }

    const float* h = (const float*)g_h4;
    int j0 = (tid & 15) * 4;
    int n0 = (tid >> 4) * 4;

    for (int tile = blockIdx.x; tile < NTH; tile += gridDim.x) {
        int base = tile * 64;
        __syncthreads();
        for (int idx = tid; idx < 64 * DH; idx += 256) {
            int row = base + (idx >> 7);
            sh[idx] = (row < NN) ? h[(size_t)row * DH + (idx & 127)] : 0.f;
        }
        __syncthreads();

        float ay[4][4], ao[4][4];
        #pragma unroll
        for (int i = 0; i < 4; i++)
            #pragma unroll
            for (int c = 0; c < 4; c++) { ay[i][c] = 0.f; ao[i][c] = 0.f; }

        #pragma unroll 4
        for (int k = 0; k < DH; k++) {
            float4 wl = *(const float4*)&sWl[k * DOUT + j0];
            float4 wr = *(const float4*)&sWr[k * DOUT + j0];
            float f[4];
            #pragma unroll
            for (int i = 0; i < 4; i++) f[i] = sh[(n0 + i) * DH + k];
            #pragma unroll
            for (int i = 0; i < 4; i++) {
                ay[i][0] = fmaf(f[i], wl.x, ay[i][0]);
                ay[i][1] = fmaf(f[i], wl.y, ay[i][1]);
                ay[i][2] = fmaf(f[i], wl.z, ay[i][2]);
                ay[i][3] = fmaf(f[i], wl.w, ay[i][3]);
                ao[i][0] = fmaf(f[i], wr.x, ao[i][0]);
                ao[i][1] = fmaf(f[i], wr.y, ao[i][1]);
                ao[i][2] = fmaf(f[i], wr.z, ao[i][2]);
                ao[i][3] = fmaf(f[i], wr.w, ao[i][3]);
            }
        }
        #pragma unroll
        for (int i = 0; i < 4; i++) {
            int row = base + n0 + i;
            if (row < NN) {
                g_y[(size_t)row * 16 + (j0 >> 2)] =
                    make_float4(ay[i][0], ay[i][1], ay[i][2], ay[i][3]);
                *(float4*)&out[(size_t)row * DOUT + j0] =
                    make_float4(ao[i][0], ao[i][1], ao[i][2], ao[i][3]);
            }
        }
    }
}

// ------------------------------------------- final: out += mean2 + b2
__global__ void final_kernel(const float* __restrict__ b2,
                             float* __restrict__ out) {
    int i = blockIdx.x * blockDim.x + threadIdx.x;   // float4 index
    if (i >= NN * 16) return;
    int c = i & 15;
    float4* out4 = (float4*)out;
    float4 o = out4[i];
    float4 m = g_mean2[i];
    float4 b = *(const float4*)&b2[c * 4];
    out4[i] = make_float4(o.x + m.x + b.x, o.y + m.y + b.y,
                          o.z + m.z + b.z, o.w + m.w + b.w);
}

// ---------------------------------------------------------------------------
extern "C" void kernel_launch(void* const* d_in, const int* in_sizes, int n_in,
                              void* d_out, int out_size) {
    const float* x   = (const float*)d_in[0];
    const float* W1l = (const float*)d_in[1];
    const float* W1r = (const float*)d_in[2];
    const float* b1  = (const float*)d_in[3];
    const float* W2l = (const float*)d_in[4];
    const float* W2r = (const float*)d_in[5];
    const float* b2  = (const float*)d_in[6];
    const int*   ei  = (const int*)d_in[7];
    float* out = (float*)d_out;

    const int L1_SMEM = (2 * DIN * DH + DH + 2 * 32 * DIN) * 4;   // 80.5 KB
    const int HM_SMEM = (2 * DH * DOUT + 64 * DH) * 4;            // 96 KB
    cudaFuncSetAttribute(layer1_kernel, cudaFuncAttributeMaxDynamicSharedMemorySize, L1_SMEM);
    cudaFuncSetAttribute(hmul_kernel,   cudaFuncAttributeMaxDynamicSharedMemorySize, HM_SMEM);

    detect_kernel<<<1, 1024>>>(ei);
    zero_cnt_kernel<<<(NN + 1023) / 1024, 1024>>>();
    convert_kernel<<<(EE + 255) / 256, 256>>>(ei);
    scan1_kernel<<<NB_SCAN, 256>>>();
    scan2_kernel<<<1, 512>>>();
    scan3_kernel<<<NB_SCAN, 256>>>();
    place_kernel<<<(EE + 255) / 256, 256>>>();
    agg1_kernel<<<592, 256>>>(x);
    layer1_kernel<<<296, 256, L1_SMEM>>>(x, W1l, W1r, b1);
    hmul_kernel<<<296, 256, HM_SMEM>>>(W2l, W2r, out);
    agg2_kernel<<<592, 256>>>();
    final_kernel<<<(NN * 16 + 255) / 256, 256>>>(b2, out);
}

// round 6
// speedup vs baseline: 9.3538x; 1.1811x over previous
#include <cuda_runtime.h>
#include <cuda_bf16.h>
#include <cstdint>

#define NN   100000
#define EE   1000000
#define DIN  64
#define DH   128
#define DOUT 64
#define NB_SCAN 391                     // ceil(NN/256)
#define NT1 ((NN + 31) / 32)            // layer1 tiles of 32 nodes
#define NTH ((NN + 63) / 64)            // hmul tiles of 64 nodes

typedef unsigned long long ull;

// ----- device scratch (no allocation allowed) -----
__device__ int    g_is64;
__device__ int    g_cnti[NN];
__device__ int    g_bsum[NB_SCAN];
__device__ int    g_boff[NB_SCAN];
__device__ int    g_off[NN + 1];
__device__ int    g_cur[NN];
__device__ float  g_inv[NN];
__device__ int    g_src[EE];
__device__ int    g_dst[EE];
__device__ int    g_esrc[EE];                      // src sorted by dst bucket
__device__ float4 g_mean1[(size_t)NN * (DIN / 4)];
__device__ float4 g_h4[(size_t)NN * (DH / 4)];
__device__ float4 g_y[(size_t)NN * (DOUT / 4)];

// ---- packed f32x2 helpers (Blackwell FFMA2 — ptxas never emits from C++) ----
__device__ __forceinline__ ull pk2(float a, float b) {
    ull r; asm("mov.b64 %0, {%1, %2};" : "=l"(r) : "f"(a), "f"(b)); return r;
}
__device__ __forceinline__ void upk2(float& a, float& b, ull v) {
    asm("mov.b64 {%0, %1}, %2;" : "=f"(a), "=f"(b) : "l"(v));
}
__device__ __forceinline__ void fma2(ull& d, ull a, ull b) {
    asm("fma.rn.f32x2 %0, %1, %2, %0;" : "+l"(d) : "l"(a), "l"(b));
}

// --------------------------------------------- detect edge_index storage width
__global__ void detect_kernel(const int* __restrict__ ei) {
    __shared__ int any_nonzero;
    if (threadIdx.x == 0) any_nonzero = 0;
    __syncthreads();
    int i = 1 + 2 * threadIdx.x;            // odd words 1..2047
    if (i < 2048 && ei[i] != 0) atomicExch(&any_nonzero, 1);
    __syncthreads();
    if (threadIdx.x == 0) g_is64 = any_nonzero ? 0 : 1;
}

__global__ void zero_cnt_kernel() {
    int i = blockIdx.x * blockDim.x + threadIdx.x;
    if (i < NN) g_cnti[i] = 0;
}

// --------------------------------- convert indices to int32 + degree histogram
__global__ void convert_kernel(const int* __restrict__ ei) {
    int e = blockIdx.x * blockDim.x + threadIdx.x;
    if (e >= EE) return;
    int is64 = g_is64;
    int s = is64 ? ei[2 * e] : ei[e];
    int d = is64 ? ei[2 * (EE + e)] : ei[EE + e];
    s = min(max(s, 0), NN - 1);
    d = min(max(d, 0), NN - 1);
    g_src[e] = s;
    g_dst[e] = d;
    atomicAdd(&g_cnti[d], 1);
}

// ------------------------------------------------------------- 3-phase scan
__global__ void scan1_kernel() {
    __shared__ int s[256];
    int i = blockIdx.x * 256 + threadIdx.x;
    s[threadIdx.x] = (i < NN) ? g_cnti[i] : 0;
    __syncthreads();
    for (int d = 128; d > 0; d >>= 1) {
        if (threadIdx.x < d) s[threadIdx.x] += s[threadIdx.x + d];
        __syncthreads();
    }
    if (threadIdx.x == 0) g_bsum[blockIdx.x] = s[0];
}

__global__ void scan2_kernel() {
    __shared__ int s[512];
    int t = threadIdx.x;
    int orig = (t < NB_SCAN) ? g_bsum[t] : 0;
    s[t] = orig;
    __syncthreads();
    for (int d = 1; d < 512; d <<= 1) {
        int v = (t >= d) ? s[t - d] : 0;
        __syncthreads();
        s[t] += v;
        __syncthreads();
    }
    if (t < NB_SCAN) g_boff[t] = s[t] - orig;
}

__global__ void scan3_kernel() {
    __shared__ int s[256];
    int t = threadIdx.x;
    int i = blockIdx.x * 256 + t;
    int c = (i < NN) ? g_cnti[i] : 0;
    s[t] = c;
    __syncthreads();
    for (int d = 1; d < 256; d <<= 1) {
        int v = (t >= d) ? s[t - d] : 0;
        __syncthreads();
        s[t] += v;
        __syncthreads();
    }
    if (i < NN) {
        int off = g_boff[blockIdx.x] + s[t] - c;
        g_off[i] = off;
        g_cur[i] = off;
        g_inv[i] = 1.0f / fmaxf((float)c, 1.0f);
    }
    if (i == 0) g_off[NN] = EE;
}

__global__ void place_kernel() {
    int e = blockIdx.x * blockDim.x + threadIdx.x;
    if (e >= EE) return;
    int pos = atomicAdd(&g_cur[g_dst[e]], 1);
    g_esrc[pos] = g_src[e];
}

// ----------------------------------- gather-aggregate: mean1 = mean x[nbrs]
__global__ void __launch_bounds__(256)
agg1_kernel(const float* __restrict__ x) {
    int gwarp = (blockIdx.x * 256 + threadIdx.x) >> 5;
    int lane = threadIdx.x & 31;
    int nw = (gridDim.x * 256) >> 5;
    int chunk = lane & 15, par = lane >> 4;
    const float4* x4 = (const float4*)x;
    for (int node = gwarp; node < NN; node += nw) {
        int s = g_off[node], e = g_off[node + 1];
        float4 acc = make_float4(0.f, 0.f, 0.f, 0.f);
        for (int i = s + par; i < e; i += 2) {
            int src = g_esrc[i];
            float4 v = x4[(size_t)src * 16 + chunk];
            acc.x += v.x; acc.y += v.y; acc.z += v.z; acc.w += v.w;
        }
        acc.x += __shfl_down_sync(0xffffffffu, acc.x, 16);
        acc.y += __shfl_down_sync(0xffffffffu, acc.y, 16);
        acc.z += __shfl_down_sync(0xffffffffu, acc.z, 16);
        acc.w += __shfl_down_sync(0xffffffffu, acc.w, 16);
        if (par == 0) {
            float inv = g_inv[node];
            g_mean1[(size_t)node * 16 + chunk] =
                make_float4(acc.x * inv, acc.y * inv, acc.z * inv, acc.w * inv);
        }
    }
}

// --------------- gather-aggregate 2 FUSED: out += mean y[nbrs] + b2
__global__ void __launch_bounds__(256)
agg2_kernel(const float* __restrict__ b2, float* __restrict__ out) {
    int gwarp = (blockIdx.x * 256 + threadIdx.x) >> 5;
    int lane = threadIdx.x & 31;
    int nw = (gridDim.x * 256) >> 5;
    int chunk = lane & 15, par = lane >> 4;
    float4* out4 = (float4*)out;
    for (int node = gwarp; node < NN; node += nw) {
        int s = g_off[node], e = g_off[node + 1];
        float4 acc = make_float4(0.f, 0.f, 0.f, 0.f);
        for (int i = s + par; i < e; i += 2) {
            int src = g_esrc[i];
            float4 v = g_y[(size_t)src * 16 + chunk];
            acc.x += v.x; acc.y += v.y; acc.z += v.z; acc.w += v.w;
        }
        acc.x += __shfl_down_sync(0xffffffffu, acc.x, 16);
        acc.y += __shfl_down_sync(0xffffffffu, acc.y, 16);
        acc.z += __shfl_down_sync(0xffffffffu, acc.z, 16);
        acc.w += __shfl_down_sync(0xffffffffu, acc.w, 16);
        if (par == 0) {
            float inv = g_inv[node];
            size_t oi = (size_t)node * 16 + chunk;
            float4 o = out4[oi];
            float4 b = *(const float4*)&b2[chunk * 4];
            out4[oi] = make_float4(o.x + acc.x * inv + b.x,
                                   o.y + acc.y * inv + b.y,
                                   o.z + acc.z * inv + b.z,
                                   o.w + acc.w * inv + b.w);
        }
    }
}

// -------------------------- layer 1: h = relu(mean1 @ W1l + x @ W1r + b1)
// 32-node tile; 256 thr = 8 node-groups(4) x 32 col-groups(4). FFMA2 packed cols.
__global__ void __launch_bounds__(256, 2)
layer1_kernel(const float* __restrict__ x,
              const float* __restrict__ W1l,
              const float* __restrict__ W1r,
              const float* __restrict__ b1) {
    extern __shared__ float smem[];
    float*  sWl   = smem;                        // DIN*DH = 32KB
    float*  sWr   = sWl + DIN * DH;              // 32KB
    float*  sb1   = sWr + DIN * DH;              // 128
    float2* sfeat = (float2*)(sb1 + DH);         // 32*DIN float2 = 16KB

    int tid = threadIdx.x;
    for (int k = tid; k < DIN * DH; k += 256) { sWl[k] = W1l[k]; sWr[k] = W1r[k]; }
    if (tid < DH) sb1[tid] = b1[tid];

    const float* mean1 = (const float*)g_mean1;
    float* h = (float*)g_h4;
    int j0 = (tid & 31) * 4;   // 4 cols (2 packed pairs)
    int n0 = (tid >> 5) * 4;   // 4 nodes

    for (int tile = blockIdx.x; tile < NT1; tile += gridDim.x) {
        int base = tile * 32;
        __syncthreads();
        for (int idx = tid; idx < 32 * DIN; idx += 256) {
            int n = idx >> 6, k = idx & 63;
            int row = base + n;
            float m = 0.f, xv = 0.f;
            if (row < NN) {
                m  = mean1[(size_t)row * DIN + k];
                xv = x[(size_t)row * DIN + k];
            }
            sfeat[n * DIN + k] = make_float2(m, xv);
        }
        __syncthreads();

        ull acc[4][2];
        {
            ull b01 = pk2(sb1[j0], sb1[j0 + 1]);
            ull b23 = pk2(sb1[j0 + 2], sb1[j0 + 3]);
            #pragma unroll
            for (int i = 0; i < 4; i++) { acc[i][0] = b01; acc[i][1] = b23; }
        }

        #pragma unroll 8
        for (int k = 0; k < DIN; k++) {
            ulonglong2 wl = *(const ulonglong2*)&sWl[k * DH + j0];  // 2 packed col-pairs
            ulonglong2 wr = *(const ulonglong2*)&sWr[k * DH + j0];
            #pragma unroll
            for (int i = 0; i < 4; i++) {
                float2 f = sfeat[(n0 + i) * DIN + k];
                ull pm  = pk2(f.x, f.x);
                ull pxv = pk2(f.y, f.y);
                fma2(acc[i][0], pm, wl.x);
                fma2(acc[i][1], pm, wl.y);
                fma2(acc[i][0], pxv, wr.x);
                fma2(acc[i][1], pxv, wr.y);
            }
        }
        #pragma unroll
        for (int i = 0; i < 4; i++) {
            int row = base + n0 + i;
            if (row < NN) {
                float a0, a1, a2, a3;
                upk2(a0, a1, acc[i][0]);
                upk2(a2, a3, acc[i][1]);
                *(float4*)&h[(size_t)row * DH + j0] =
                    make_float4(fmaxf(a0, 0.f), fmaxf(a1, 0.f),
                                fmaxf(a2, 0.f), fmaxf(a3, 0.f));
            }
        }
    }
}

// ---------------- fused: y = h @ W2l ; out_partial = h @ W2r
// 64-node tile; 256 thr = 16 node-groups(4) x 16 col-groups(4). FFMA2 packed cols.
__global__ void __launch_bounds__(256, 2)
hmul_kernel(const float* __restrict__ W2l,
            const float* __restrict__ W2r,
            float* __restrict__ out) {
    extern __shared__ float smem[];
    float* sWl = smem;                  // DH*DOUT = 32KB
    float* sWr = sWl + DH * DOUT;       // 32KB
    float* sh  = sWr + DH * DOUT;       // 64*DH = 32KB

    int tid = threadIdx.x;
    for (int k = tid; k < DH * DOUT; k += 256) { sWl[k] = W2l[k]; sWr[k] = W2r[k]; }

    const float* h = (const float*)g_h4;
    int j0 = (tid & 15) * 4;
    int n0 = (tid >> 4) * 4;

    for (int tile = blockIdx.x; tile < NTH; tile += gridDim.x) {
        int base = tile * 64;
        __syncthreads();
        for (int idx = tid; idx < 64 * DH; idx += 256) {
            int row = base + (idx >> 7);
            sh[idx] = (row < NN) ? h[(size_t)row * DH + (idx & 127)] : 0.f;
        }
        __syncthreads();

        ull ay[4][2], ao[4][2];
        #pragma unroll
        for (int i = 0; i < 4; i++) {
            ay[i][0] = 0ull; ay[i][1] = 0ull;
            ao[i][0] = 0ull; ao[i][1] = 0ull;
        }

        #pragma unroll 4
        for (int k = 0; k < DH; k++) {
            ulonglong2 wl = *(const ulonglong2*)&sWl[k * DOUT + j0];
            ulonglong2 wr = *(const ulonglong2*)&sWr[k * DOUT + j0];
            #pragma unroll
            for (int i = 0; i < 4; i++) {
                float f = sh[(n0 + i) * DH + k];
                ull pf = pk2(f, f);
                fma2(ay[i][0], pf, wl.x);
                fma2(ay[i][1], pf, wl.y);
                fma2(ao[i][0], pf, wr.x);
                fma2(ao[i][1], pf, wr.y);
            }
        }
        #pragma unroll
        for (int i = 0; i < 4; i++) {
            int row = base + n0 + i;
            if (row < NN) {
                float y0, y1, y2, y3, o0, o1, o2, o3;
                upk2(y0, y1, ay[i][0]); upk2(y2, y3, ay[i][1]);
                upk2(o0, o1, ao[i][0]); upk2(o2, o3, ao[i][1]);
                g_y[(size_t)row * 16 + (j0 >> 2)] = make_float4(y0, y1, y2, y3);
                *(float4*)&out[(size_t)row * DOUT + j0] = make_float4(o0, o1, o2, o3);
            }
        }
    }
}

// ---------------------------------------------------------------------------
extern "C" void kernel_launch(void* const* d_in, const int* in_sizes, int n_in,
                              void* d_out, int out_size) {
    const float* x   = (const float*)d_in[0];
    const float* W1l = (const float*)d_in[1];
    const float* W1r = (const float*)d_in[2];
    const float* b1  = (const float*)d_in[3];
    const float* W2l = (const float*)d_in[4];
    const float* W2r = (const float*)d_in[5];
    const float* b2  = (const float*)d_in[6];
    const int*   ei  = (const int*)d_in[7];
    float* out = (float*)d_out;

    const int L1_SMEM = (2 * DIN * DH + DH + 2 * 32 * DIN) * 4;   // 80.5 KB
    const int HM_SMEM = (2 * DH * DOUT + 64 * DH) * 4;            // 96 KB
    cudaFuncSetAttribute(layer1_kernel, cudaFuncAttributeMaxDynamicSharedMemorySize, L1_SMEM);
    cudaFuncSetAttribute(hmul_kernel,   cudaFuncAttributeMaxDynamicSharedMemorySize, HM_SMEM);

    detect_kernel<<<1, 1024>>>(ei);
    zero_cnt_kernel<<<(NN + 1023) / 1024, 1024>>>();
    convert_kernel<<<(EE + 255) / 256, 256>>>(ei);
    scan1_kernel<<<NB_SCAN, 256>>>();
    scan2_kernel<<<1, 512>>>();
    scan3_kernel<<<NB_SCAN, 256>>>();
    place_kernel<<<(EE + 255) / 256, 256>>>();
    agg1_kernel<<<592, 256>>>(x);
    layer1_kernel<<<296, 256, L1_SMEM>>>(x, W1l, W1r, b1);
    hmul_kernel<<<296, 256, HM_SMEM>>>(W2l, W2r, out);
    agg2_kernel<<<592, 256>>>(b2, out);
}